// round 8
// baseline (speedup 1.0000x reference)
#include <cuda_runtime.h>
#include <math.h>

#define RES       256
#define NPIX      (RES*RES)       // 65536 pixels per camera
#define NQUAD     (NPIX/4)        // 16384 float4-groups per camera
#define NCAM      32
#define NB        64
#define CAMCHUNK  56              // grid 1792 = single wave @13 blocks/SM
#define TPB       64
#define NWARP     (TPB/32)        // 2
#define ROWS      66              // row 0: dummy(k<0); 1..64: bins 0..63; 65: dummy(k>=64)
#define WIN       7               // bins kc-3 .. kc+3

__global__ void spad_zero_out(float* __restrict__ out) {
    int i = blockIdx.x * blockDim.x + threadIdx.x;
    if (i < NCAM * NB) out[i] = 0.0f;
}

__global__ __launch_bounds__(TPB, 13) void spad_main(
    const float* __restrict__ normals,
    const float* __restrict__ inter,
    const float* __restrict__ film,
    const float* __restrict__ cosm,
    float* __restrict__ out,
    float radC, float inv2sig2, float halfInvBin)
{
    // per-(warp,lane) private difference-histograms: bank == lane, conflict-free
    __shared__ float sh[NWARP][ROWS][32];

    const int tid  = threadIdx.x;
    const int lane = tid & 31;
    const int wid  = tid >> 5;

    for (int i = tid; i < NWARP * ROWS * 32; i += TPB)
        ((float*)sh)[i] = 0.0f;
    __syncthreads();

    const int cam   = blockIdx.x / CAMCHUNK;
    const int chunk = blockIdx.x % CAMCHUNK;
    const int qs    = (NQUAD * chunk)       / CAMCHUNK;
    const int qe    = (NQUAD * (chunk + 1)) / CAMCHUNK;

    const float4* n4 = (const float4*)(normals + (size_t)cam * NPIX * 3);
    const float4* p4 = (const float4*)(inter   + (size_t)cam * NPIX * 3);
    const float4* f4 = (const float4*)film;
    const float4* c4 = (const float4*)cosm;

    float* Wbase = &sh[wid][0][lane];

    const float E3 = 20.085536923187668f;   // e^3

    for (int q = qs + tid; q < qe; q += TPB) {
        float4 nA = n4[q*3+0], nB = n4[q*3+1], nC = n4[q*3+2];
        float4 pA = p4[q*3+0], pB = p4[q*3+1], pC = p4[q*3+2];
        float4 fA = f4[q*3+0], fB = f4[q*3+1], fC = f4[q*3+2];
        float4 cV = c4[q];

        float n_[12], p_[12], f_[12], c_[4];
        *(float4*)&n_[0] = nA; *(float4*)&n_[4] = nB; *(float4*)&n_[8] = nC;
        *(float4*)&p_[0] = pA; *(float4*)&p_[4] = pB; *(float4*)&p_[8] = pC;
        *(float4*)&f_[0] = fA; *(float4*)&f_[4] = fB; *(float4*)&f_[8] = fC;
        c_[0] = cV.x; c_[1] = cV.y; c_[2] = cV.z; c_[3] = cV.w;

        float  rA[4], GA[4], prevA[4];
        int    rowA[4];
        bool   fast = true;

        #pragma unroll
        for (int u = 0; u < 4; ++u) {
            const float nx = n_[3*u], ny = n_[3*u+1], nz = n_[3*u+2];
            const float px = p_[3*u], py = p_[3*u+1], pz = p_[3*u+2];
            const float fx = f_[3*u], fy = f_[3*u+1], fz = f_[3*u+2];
            const float cm = c_[u];

            float dots = fminf(fmaxf(fx*nx + fy*ny + fz*nz, 0.0f), 1.0f);

            const float lx = px - 0.002f;     // 2 * camera_sensor_distance
            const float ly = py;
            const float lz = pz;
            const float lxy2 = lx*lx + ly*ly;
            const float ld2  = lxy2 + lz*lz;
            const float ld   = sqrtf(ld2);
            const float tan2 = __fdividef(lxy2, lz*lz);
            const float lm   = __expf(-tan2 * inv2sig2);

            const float pd  = sqrtf(px*px + py*py + pz*pz);
            const float cm3 = cm * cm * cm;
            const float r   = dots * lm * cm3 * __fdividef(radC, ld2);
            const float d   = (pd + ld) * halfInvBin;   // bin coordinate (>= 0)

            const int kc = __float2int_rd(d);

            // 7-bin window kc-3..kc+3: bin b gets r*(S_b - S_{b+1}).
            // S_{kc-3} ~= 1 (err ~ e^-9), dropped tail r*S_{kc+4} <= 1.2e-4*r.
            rA[u]    = r;
            GA[u]    = __expf(3.0f * ((float)kc - d - 3.0f));
            prevA[u] = r;
            rowA[u]  = kc - 2;                 // smem row of bin kc-3 (bin b -> row b+1)
            fast &= (kc >= 3) & (kc <= 60);
        }

        if (fast) {
            // interleaved pointer walk: 4 independent RMW chains per j-step
            float* w0 = Wbase + (rowA[0] << 5);
            float* w1 = Wbase + (rowA[1] << 5);
            float* w2 = Wbase + (rowA[2] << 5);
            float* w3 = Wbase + (rowA[3] << 5);
            #pragma unroll
            for (int j = 0; j < WIN; ++j) {
                GA[0] *= E3; GA[1] *= E3; GA[2] *= E3; GA[3] *= E3;
                const float S0 = __fdividef(rA[0], 1.0f + GA[0]);
                const float S1 = __fdividef(rA[1], 1.0f + GA[1]);
                const float S2 = __fdividef(rA[2], 1.0f + GA[2]);
                const float S3 = __fdividef(rA[3], 1.0f + GA[3]);
                *w0 += prevA[0] - S0;  w0 += 32;  prevA[0] = S0;
                *w1 += prevA[1] - S1;  w1 += 32;  prevA[1] = S1;
                *w2 += prevA[2] - S2;  w2 += 32;  prevA[2] = S2;
                *w3 += prevA[3] - S3;  w3 += 32;  prevA[3] = S3;
            }
        } else {
            // rare path: clamp out-of-range rows into dummy rows 0 / 65
            #pragma unroll
            for (int u = 0; u < 4; ++u) {
                int row = rowA[u];
                #pragma unroll
                for (int j = 0; j < WIN; ++j) {
                    GA[u] *= E3;
                    const float S  = __fdividef(rA[u], 1.0f + GA[u]);
                    const int   rb = min(max(row, 0), 65);
                    Wbase[rb << 5] += prevA[u] - S;
                    prevA[u] = S; ++row;
                }
            }
        }
    }
    __syncthreads();

    // fold warp 1 into warp 0
    float* s0 = (float*)sh;
    for (int i = tid; i < ROWS * 32; i += TPB)
        s0[i] += s0[i + ROWS * 32];
    __syncthreads();

    // lane-rotated conflict-free reduction; bins 0..63 live in rows 1..64
    if (tid < NB) {
        float s = 0.0f;
        #pragma unroll
        for (int l = 0; l < 32; ++l)
            s += sh[0][tid + 1][(l + tid) & 31];
        atomicAdd(&out[cam * NB + tid], s);
    }
}

extern "C" void kernel_launch(void* const* d_in, const int* in_sizes, int n_in,
                              void* d_out, int out_size) {
    const float* normals = (const float*)d_in[0];   // [32,256,256,3]
    const float* inter   = (const float*)d_in[1];   // [32,256,256,3]
    const float* film    = (const float*)d_in[2];   // [256,256,3]
    const float* cosm    = (const float*)d_in[3];   // [256,256]
    float* out = (float*)d_out;                     // [32,64]

    const double fov    = 33.0 * M_PI / 180.0;
    const double width  = 2.0 * tan(fov / 2.0);
    const float  radC   = (float)(width * width / (M_PI * (double)NPIX));
    const double sig    = tan(21.5 * M_PI / 180.0) / 1.4;
    const float  inv2s2 = (float)(1.0 / (2.0 * sig * sig));
    const float  hib    = (float)(0.5 / 0.0136);    // (1/2) / bin_size

    spad_zero_out<<<(NCAM * NB + 255) / 256, 256>>>(out);
    spad_main<<<NCAM * CAMCHUNK, TPB>>>(normals, inter, film, cosm, out,
                                        radC, inv2s2, hib);
    (void)in_sizes; (void)n_in; (void)out_size;
}

// round 9
// speedup vs baseline: 1.0976x; 1.0976x over previous
#include <cuda_runtime.h>
#include <math.h>

#define RES       256
#define NPIX      (RES*RES)       // 65536 pixels per camera
#define NQUAD     (NPIX/4)        // 16384 float4-groups per camera
#define NCAM      32
#define NB        64
#define CAMCHUNK  55              // grid 1760 = single wave @12 blocks/SM
#define TPB       64
#define NWARP     (TPB/32)        // 2
#define ROWS      66              // row 0: dummy(k<0); 1..64: bins 0..63; 65: dummy(k>=64)

__global__ void spad_zero_out(float* __restrict__ out) {
    int i = blockIdx.x * blockDim.x + threadIdx.x;
    if (i < NCAM * NB) out[i] = 0.0f;
}

__global__ __launch_bounds__(TPB, 12) void spad_main(
    const float* __restrict__ normals,
    const float* __restrict__ inter,
    const float* __restrict__ film,
    const float* __restrict__ cosm,
    float* __restrict__ out,
    float radC, float inv2sig2, float halfInvBin)
{
    // per-(warp,lane) private difference-histograms: bank == lane, conflict-free
    __shared__ float sh[NWARP][ROWS][32];

    const int tid  = threadIdx.x;
    const int lane = tid & 31;
    const int wid  = tid >> 5;

    for (int i = tid; i < NWARP * ROWS * 32; i += TPB)
        ((float*)sh)[i] = 0.0f;
    __syncthreads();

    const int cam   = blockIdx.x / CAMCHUNK;
    const int chunk = blockIdx.x % CAMCHUNK;
    const int qs    = (NQUAD * chunk)       / CAMCHUNK;
    const int qe    = (NQUAD * (chunk + 1)) / CAMCHUNK;

    const float4* n4 = (const float4*)(normals + (size_t)cam * NPIX * 3);
    const float4* p4 = (const float4*)(inter   + (size_t)cam * NPIX * 3);
    const float4* f4 = (const float4*)film;
    const float4* c4 = (const float4*)cosm;

    float* Wbase = &sh[wid][0][lane];

    const float E3 = 20.085536923187668f;   // e^3

    for (int q = qs + tid; q < qe; q += TPB) {
        float4 nA = n4[q*3+0], nB = n4[q*3+1], nC = n4[q*3+2];
        float4 pA = p4[q*3+0], pB = p4[q*3+1], pC = p4[q*3+2];
        float4 fA = f4[q*3+0], fB = f4[q*3+1], fC = f4[q*3+2];
        float4 cV = c4[q];

        float n_[12], p_[12], f_[12], c_[4];
        *(float4*)&n_[0] = nA; *(float4*)&n_[4] = nB; *(float4*)&n_[8] = nC;
        *(float4*)&p_[0] = pA; *(float4*)&p_[4] = pB; *(float4*)&p_[8] = pC;
        *(float4*)&f_[0] = fA; *(float4*)&f_[4] = fB; *(float4*)&f_[8] = fC;
        c_[0] = cV.x; c_[1] = cV.y; c_[2] = cV.z; c_[3] = cV.w;

        #pragma unroll
        for (int u = 0; u < 4; ++u) {
            const float nx = n_[3*u], ny = n_[3*u+1], nz = n_[3*u+2];
            const float px = p_[3*u], py = p_[3*u+1], pz = p_[3*u+2];
            const float fx = f_[3*u], fy = f_[3*u+1], fz = f_[3*u+2];
            const float cm = c_[u];

            float dots = fminf(fmaxf(fx*nx + fy*ny + fz*nz, 0.0f), 1.0f);

            const float lx = px - 0.002f;     // 2 * camera_sensor_distance
            const float ly = py;
            const float lz = pz;
            const float lxy2 = lx*lx + ly*ly;
            const float ld2  = lxy2 + lz*lz;

            // rsqrt gives both ld and 1/ld2 in one MUFU
            const float rld   = rsqrtf(ld2);
            const float ld    = ld2 * rld;
            const float ild2  = rld * rld;
            const float ilz2  = __fdividef(1.0f, lz * lz);           // MUFU.RCP
            const float lm    = __expf(-lxy2 * inv2sig2 * ilz2);     // MUFU.EX2

            const float pd  = sqrtf(px*px + py*py + pz*pz);          // MUFU.SQRT
            const float cm3 = cm * cm * cm;
            const float r   = dots * lm * cm3 * radC * ild2;
            const float d   = (pd + ld) * halfInvBin;                // bin coordinate

            const int kc = __float2int_rd(d);

            // 7-bin window kc-3..kc+3; S_j = r*sigmoid(3(d-kc+2-j)), j=0..6.
            // Batch inversion: ONE rcp for all 7 sigmoid denominators.
            float G  = __expf(3.0f * ((float)kc - d - 2.0f));        // MUFU.EX2
            const float D0 = 1.0f + G;  G *= E3;
            const float D1 = 1.0f + G;  G *= E3;
            const float D2 = 1.0f + G;  G *= E3;
            const float D3 = 1.0f + G;  G *= E3;
            const float D4 = 1.0f + G;  G *= E3;
            const float D5 = 1.0f + G;  G *= E3;
            const float D6 = 1.0f + G;                               // max ~1+e^12

            const float P0 = D0;
            const float P1 = P0 * D1;
            const float P2 = P1 * D2;
            const float P3 = P2 * D3;
            const float P4 = P3 * D4;
            const float P5 = P4 * D5;
            const float P6 = P5 * D6;                                // <= ~1.1e13

            float R = __fdividef(r, P6);                             // MUFU.RCP (batched)
            const float S6 = P5 * R;  R *= D6;                       // R = r/P5
            const float S5 = P4 * R;  R *= D5;
            const float S4 = P3 * R;  R *= D4;
            const float S3 = P2 * R;  R *= D3;
            const float S2 = P1 * R;  R *= D2;
            const float S1 = P0 * R;  R *= D1;
            const float S0 = R;                                      // r/D0

            if (kc >= 3 && kc <= 60) {
                float* w = Wbase + ((kc - 2) << 5);   // row of bin kc-3
                w[0*32] += r  - S0;
                w[1*32] += S0 - S1;
                w[2*32] += S1 - S2;
                w[3*32] += S2 - S3;
                w[4*32] += S3 - S4;
                w[5*32] += S4 - S5;
                w[6*32] += S5 - S6;
            } else {
                const float Ss[7] = {S0, S1, S2, S3, S4, S5, S6};
                float Sm = r;
                const int b = kc - 2;
                #pragma unroll
                for (int j = 0; j < 7; ++j) {
                    const int rb = min(max(b + j, 0), 65);
                    Wbase[rb << 5] += Sm - Ss[j];
                    Sm = Ss[j];
                }
            }
        }
    }
    __syncthreads();

    // fold warp 1 into warp 0
    float* s0 = (float*)sh;
    for (int i = tid; i < ROWS * 32; i += TPB)
        s0[i] += s0[i + ROWS * 32];
    __syncthreads();

    // lane-rotated conflict-free reduction; bins 0..63 live in rows 1..64
    if (tid < NB) {
        float s = 0.0f;
        #pragma unroll
        for (int l = 0; l < 32; ++l)
            s += sh[0][tid + 1][(l + tid) & 31];
        atomicAdd(&out[cam * NB + tid], s);
    }
}

extern "C" void kernel_launch(void* const* d_in, const int* in_sizes, int n_in,
                              void* d_out, int out_size) {
    const float* normals = (const float*)d_in[0];   // [32,256,256,3]
    const float* inter   = (const float*)d_in[1];   // [32,256,256,3]
    const float* film    = (const float*)d_in[2];   // [256,256,3]
    const float* cosm    = (const float*)d_in[3];   // [256,256]
    float* out = (float*)d_out;                     // [32,64]

    const double fov    = 33.0 * M_PI / 180.0;
    const double width  = 2.0 * tan(fov / 2.0);
    const float  radC   = (float)(width * width / (M_PI * (double)NPIX));
    const double sig    = tan(21.5 * M_PI / 180.0) / 1.4;
    const float  inv2s2 = (float)(1.0 / (2.0 * sig * sig));
    const float  hib    = (float)(0.5 / 0.0136);    // (1/2) / bin_size

    spad_zero_out<<<(NCAM * NB + 255) / 256, 256>>>(out);
    spad_main<<<NCAM * CAMCHUNK, TPB>>>(normals, inter, film, cosm, out,
                                        radC, inv2s2, hib);
    (void)in_sizes; (void)n_in; (void)out_size;
}